// round 8
// baseline (speedup 1.0000x reference)
#include <cuda_runtime.h>
#include <cuda_fp16.h>
#include <cstdint>
#include <math_constants.h>

#define NSTEPS 512
#define KDIM   513
#define BATCH  65536
#define COLS   512
#define NSEG   8           // 8 segments x 64 steps
#define NQUAD  128         // 4-step quads
#define RPB    32          // rows per mega block

#define PREP_BLOCKS 1024   // 128 quads x 8 p-chunks of 64

// Persistent tables (~2 MB).
__device__ __half g_T4[NQUAD * COLS * 16];  // fused 4-step log table (fp16)
__device__ float  g_logE[KDIM];

// ---------------------------------------------------------------------------
// Kernel 1: build T4. Block = (quad i, 64-wide p-chunk). The 4x68 window of
// log-softmaxes is computed ONCE into smem; each thread then combines 4
// bit-combos for one p (16 smem adds) and stores 8 B coalesced.
// T4[i][p][c] = sum_{k=0..3} [1 <= q_k <= 4i+k] * LS[4i+k-1][q_k-1][b_k],
//   b_k = bit k of c, q_k = p + popc(c & ((1<<(k+1))-1)).
// Block PREP_BLOCKS does logsoftmax(endW).
// ---------------------------------------------------------------------------
__global__ void __launch_bounds__(256) prep_kernel(
        const float* __restrict__ W, const float* __restrict__ endW) {
    if (blockIdx.x == PREP_BLOCKS) {
        if (threadIdx.x < 32) {
            int lane = threadIdx.x;
            float m = -CUDART_INF_F;
            for (int k = lane; k < KDIM; k += 32) m = fmaxf(m, endW[k]);
            #pragma unroll
            for (int o = 16; o; o >>= 1) m = fmaxf(m, __shfl_xor_sync(0xffffffffu, m, o));
            float s = 0.f;
            for (int k = lane; k < KDIM; k += 32) s += __expf(endW[k] - m);
            #pragma unroll
            for (int o = 16; o; o >>= 1) s += __shfl_xor_sync(0xffffffffu, s, o);
            float lse = m + __logf(s);
            for (int k = lane; k < KDIM; k += 32) g_logE[k] = endW[k] - lse;
        }
        return;
    }

    int i     = blockIdx.x >> 3;          // quad index [0,128)
    int pbase = (blockIdx.x & 7) << 6;    // p-chunk base

    // ls[k][jj][b]: log-softmax for step t=4i+k at column j = pbase-1+jj.
    __shared__ float ls[4][68][2];

    for (int idx = threadIdx.x; idx < 4 * 68; idx += 256) {
        int k  = idx >> 6;                 // idx / 68 would misindex; use exact:
        k = idx / 68;
        int jj = idx - k * 68;
        int t  = 4 * i + k;
        int j  = pbase - 1 + jj;
        float l0 = 0.f, l1 = 0.f;
        if (j >= 0 && j <= t - 1) {
            float w0 = W[((size_t)(t - 1) * COLS + j) * 2 + 0];
            float w1 = W[((size_t)(t - 1) * COLS + j) * 2 + 1];
            float m  = fmaxf(w0, w1);
            float lse = m + __logf(1.f + __expf(-fabsf(w0 - w1)));
            l0 = w0 - lse;
            l1 = w1 - lse;
        }
        ls[k][jj][0] = l0;
        ls[k][jj][1] = l1;
    }
    __syncthreads();

    int p    = pbase + (threadIdx.x >> 2);
    int cgrp = (threadIdx.x & 3) * 4;     // 4 combos per thread
    float v4[4];
    #pragma unroll
    for (int lo = 0; lo < 4; ++lo) {
        int c = cgrp + lo;
        int q = p;
        float v = 0.f;
        #pragma unroll
        for (int k = 0; k < 4; ++k) {
            int b  = (c >> k) & 1;
            int qn = q + b;
            int t  = 4 * i + k;
            if (qn >= 1 && qn <= t) v += ls[k][qn - pbase][b];
            q = qn;
        }
        v4[lo] = v;
    }
    __align__(8) __half2 hv[2];
    hv[0] = __floats2half2_rn(v4[0], v4[1]);
    hv[1] = __floats2half2_rn(v4[2], v4[3]);
    // 8 B per thread, consecutive threads contiguous -> fully coalesced.
    *reinterpret_cast<uint2*>(&g_T4[(((size_t)i * COLS + p) * 16) + cgrp]) =
        *reinterpret_cast<const uint2*>(hv);
}

// ---------------------------------------------------------------------------
// Kernel 2: mega kernel. Block = 32 rows, 256 threads.
//   Phase 1: warp w packs rows [w*4,w*4+4) (coalesced int4) -> smem bits +
//            per-64-step prefix popcounts.
//   Phase 2: thread (warp=seg, lane=row) walks 64 steps = 16 quad-gathers,
//            fully unrolled over a 64-bit word for max MLP.
//   Phase 3: fixed-order reduce, warp 0 writes.
// ---------------------------------------------------------------------------
__global__ void __launch_bounds__(256) mega_kernel(
        const int* __restrict__ x, float* __restrict__ out) {
    __shared__ unsigned int s_words[RPB][17];
    __shared__ int          s_ps[RPB][9];
    __shared__ float        s_part[NSEG][RPB];

    const unsigned F = 0xffffffffu;
    int w    = threadIdx.x >> 5;
    int lane = threadIdx.x & 31;
    int r0   = blockIdx.x * RPB;

    // ---- Phase 1: pack ----
    #pragma unroll 1
    for (int i = 0; i < 4; ++i) {
        int row_local = w * 4 + i;
        const int4* __restrict__ xr =
            (const int4*)(x + (size_t)(r0 + row_local) * NSTEPS);

        unsigned int words[4];
        int hv[8];
        #pragma unroll
        for (int it = 0; it < 4; ++it) {
            int4 v = xr[it * 32 + lane];
            unsigned int nib = (unsigned)(v.x != 0)
                             | ((unsigned)(v.y != 0) << 1)
                             | ((unsigned)(v.z != 0) << 2)
                             | ((unsigned)(v.w != 0) << 3);
            unsigned int part = nib << ((lane & 7) * 4);
            part |= __shfl_xor_sync(F, part, 1);
            part |= __shfl_xor_sync(F, part, 2);
            part |= __shfl_xor_sync(F, part, 4);
            words[it] = part;

            int pc = __popc(nib);            // xor 1,2,4,8 stays in 16 lanes
            pc += __shfl_xor_sync(F, pc, 1);
            pc += __shfl_xor_sync(F, pc, 2);
            pc += __shfl_xor_sync(F, pc, 4);
            pc += __shfl_xor_sync(F, pc, 8);
            hv[it * 2 + 0] = __shfl_sync(F, pc, 0);
            hv[it * 2 + 1] = __shfl_sync(F, pc, 16);
        }
        if ((lane & 7) == 0) {
            int g = lane >> 3;
            #pragma unroll
            for (int it = 0; it < 4; ++it)
                s_words[row_local][it * 4 + g] = words[it];
        }
        if (lane < NSEG) {
            int ps = 0;
            #pragma unroll
            for (int j = 0; j < NSEG - 1; ++j) if (j < lane) ps += hv[j];
            s_ps[row_local][lane] = ps;
        }
    }
    __syncthreads();

    // ---- Phase 2: walk. seg = w, row = lane. 16 quad-gathers, one stream ----
    int p = s_ps[lane][w];
    uint64_t word = (uint64_t)s_words[lane][2 * w + 0]
                  | ((uint64_t)s_words[lane][2 * w + 1] << 32);

    const __half* __restrict__ T = g_T4 + (size_t)(w * 16) * 8192;
    unsigned hq = (unsigned)p << 4;          // running index, multiple of 16
    float acc0 = 0.f, acc1 = 0.f;

    #pragma unroll
    for (int k = 0; k < 16; ++k) {
        unsigned c = (unsigned)(word >> (4 * k)) & 15u;
        float v = __half2float(__ldg(&T[k * 8192 + (hq | c)]));
        if (k & 1) acc1 += v; else acc0 += v;
        hq += (unsigned)__popc(c) << 4;
    }

    float acc = acc0 + acc1;
    if (w == NSEG - 1) acc += g_logE[hq >> 4];   // total popcount
    s_part[w][lane] = acc;
    __syncthreads();

    // ---- Phase 3: fixed-order reduce ----
    if (w == 0) {
        float s = 0.f;
        #pragma unroll
        for (int j = 0; j < NSEG; ++j) s += s_part[j][lane];
        out[r0 + lane] = s;
    }
}

// ---------------------------------------------------------------------------
extern "C" void kernel_launch(void* const* d_in, const int* in_sizes, int n_in,
                              void* d_out, int out_size) {
    const int*   x    = (const int*)  d_in[0];   // (65536, 512) int32
    const float* W    = (const float*)d_in[1];   // (511, 512, 2) float32
    const float* endW = (const float*)d_in[2];   // (1, 513) float32
    float* out = (float*)d_out;

    (void)in_sizes; (void)n_in; (void)out_size;

    prep_kernel<<<PREP_BLOCKS + 1, 256>>>(W, endW);
    mega_kernel<<<BATCH / RPB, 256>>>(x, out);
}

// round 9
// speedup vs baseline: 1.0394x; 1.0394x over previous
#include <cuda_runtime.h>
#include <cuda_fp16.h>
#include <cstdint>
#include <math_constants.h>

#define NSTEPS 512
#define KDIM   513
#define BATCH  65536
#define COLS   512
#define NSEG   8           // 8 segments x 64 steps
#define NQUAD  128         // 4-step quads
#define RPB    32          // rows per block

#define PREP_T4_BLOCKS 512 // 128 quads x 4 p-chunks of 128
#define PREP_TOTAL     513 // + endW block

// Persistent tables (~2 MB) + barrier state.
__device__ __half g_T4[NQUAD * COLS * 16];  // fused 4-step log table (fp16)
__device__ float  g_logE[KDIM];
__device__ int    g_done;                   // prep completion counter
__device__ int    g_fin;                    // block completion counter

// ---------------------------------------------------------------------------
// Single fused kernel.
//   Phase 0 (blocks <513 only): build T4 / logE. All 513 prep blocks are
//     guaranteed resident (launch_bounds(256,4) => >=592 resident blocks),
//     so the g_done spin below cannot deadlock.
//   Phase 1 (all blocks): pack 32 rows of x into smem bits + prefix popcounts
//     (doesn't need T4 -> runs before the barrier, hides prep latency).
//   Barrier: wait until all 513 prep blocks arrived.
//   Phase 2: thread (warp=seg, lane=row) walks 64 steps = 16 quad-gathers.
//   Phase 3: fixed-order reduce; counter reset protocol for graph replay.
// ---------------------------------------------------------------------------
__global__ void __launch_bounds__(256, 4) mega_kernel(
        const int* __restrict__ x, const float* __restrict__ W,
        const float* __restrict__ endW, float* __restrict__ out) {
    __shared__ float        ls[4][132][2];     // prep softmax window
    __shared__ unsigned int s_words[RPB][17];
    __shared__ int          s_ps[RPB][9];
    __shared__ float        s_part[NSEG][RPB];

    const unsigned F = 0xffffffffu;
    int tid  = threadIdx.x;
    int w    = tid >> 5;
    int lane = tid & 31;
    int bid  = blockIdx.x;
    int r0   = bid * RPB;

    // ---- Phase 0: table prep on the first 513 blocks ----
    if (bid < PREP_T4_BLOCKS) {
        int i     = bid >> 2;              // quad index [0,128)
        int pbase = (bid & 3) << 7;        // 128-wide p-chunk

        // ls[k][jj][b] = log-softmax of W[4i+k-1][pbase-1+jj][b] (0 outside)
        for (int idx = tid; idx < 4 * 132; idx += 256) {
            int k  = idx / 132;
            int jj = idx - k * 132;
            int t  = 4 * i + k;
            int j  = pbase - 1 + jj;
            float l0 = 0.f, l1 = 0.f;
            if (j >= 0 && j <= t - 1) {
                float w0 = W[((size_t)(t - 1) * COLS + j) * 2 + 0];
                float w1 = W[((size_t)(t - 1) * COLS + j) * 2 + 1];
                float m  = fmaxf(w0, w1);
                float lse = m + __logf(1.f + __expf(-fabsf(w0 - w1)));
                l0 = w0 - lse;
                l1 = w1 - lse;
            }
            ls[k][jj][0] = l0;
            ls[k][jj][1] = l1;
        }
        __syncthreads();

        // Each thread: one p, 8 combos -> 16 B coalesced store.
        int p    = pbase + (tid >> 1);
        int cgrp = (tid & 1) * 8;
        __align__(16) __half2 hv[4];
        #pragma unroll
        for (int cp = 0; cp < 4; ++cp) {
            float v2[2];
            #pragma unroll
            for (int lo = 0; lo < 2; ++lo) {
                int c = cgrp + cp * 2 + lo;
                int q = p;
                float v = 0.f;
                #pragma unroll
                for (int k = 0; k < 4; ++k) {
                    int b  = (c >> k) & 1;
                    int qn = q + b;
                    int t  = 4 * i + k;
                    if (qn >= 1 && qn <= t) v += ls[k][qn - pbase][b];
                    q = qn;
                }
                v2[lo] = v;
            }
            hv[cp] = __floats2half2_rn(v2[0], v2[1]);
        }
        *reinterpret_cast<uint4*>(&g_T4[(((size_t)i * COLS + p) * 16) + cgrp]) =
            *reinterpret_cast<const uint4*>(hv);

        __syncthreads();
        __threadfence();
        if (tid == 0) atomicAdd(&g_done, 1);
    } else if (bid == PREP_T4_BLOCKS) {
        if (tid < 32) {
            float m = -CUDART_INF_F;
            for (int k = tid; k < KDIM; k += 32) m = fmaxf(m, endW[k]);
            #pragma unroll
            for (int o = 16; o; o >>= 1) m = fmaxf(m, __shfl_xor_sync(F, m, o));
            float s = 0.f;
            for (int k = tid; k < KDIM; k += 32) s += __expf(endW[k] - m);
            #pragma unroll
            for (int o = 16; o; o >>= 1) s += __shfl_xor_sync(F, s, o);
            float lse = m + __logf(s);
            for (int k = tid; k < KDIM; k += 32) g_logE[k] = endW[k] - lse;
        }
        __syncthreads();
        __threadfence();
        if (tid == 0) atomicAdd(&g_done, 1);
    }

    // ---- Phase 1: pack (independent of T4) ----
    #pragma unroll 2
    for (int i = 0; i < 4; ++i) {
        int row_local = w * 4 + i;
        const int4* __restrict__ xr =
            (const int4*)(x + (size_t)(r0 + row_local) * NSTEPS);

        unsigned int words[4];
        int hv[8];
        #pragma unroll
        for (int it = 0; it < 4; ++it) {
            int4 v = xr[it * 32 + lane];
            unsigned int nib = (unsigned)(v.x != 0)
                             | ((unsigned)(v.y != 0) << 1)
                             | ((unsigned)(v.z != 0) << 2)
                             | ((unsigned)(v.w != 0) << 3);
            unsigned int part = nib << ((lane & 7) * 4);
            part |= __shfl_xor_sync(F, part, 1);
            part |= __shfl_xor_sync(F, part, 2);
            part |= __shfl_xor_sync(F, part, 4);
            words[it] = part;

            int pc = __popc(nib);            // xor 1,2,4,8 stays in 16 lanes
            pc += __shfl_xor_sync(F, pc, 1);
            pc += __shfl_xor_sync(F, pc, 2);
            pc += __shfl_xor_sync(F, pc, 4);
            pc += __shfl_xor_sync(F, pc, 8);
            hv[it * 2 + 0] = __shfl_sync(F, pc, 0);
            hv[it * 2 + 1] = __shfl_sync(F, pc, 16);
        }
        if ((lane & 7) == 0) {
            int g = lane >> 3;
            #pragma unroll
            for (int it = 0; it < 4; ++it)
                s_words[row_local][it * 4 + g] = words[it];
        }
        if (lane < NSEG) {
            int ps = 0;
            #pragma unroll
            for (int j = 0; j < NSEG - 1; ++j) if (j < lane) ps += hv[j];
            s_ps[row_local][lane] = ps;
        }
    }
    __syncthreads();

    // ---- Barrier: wait for table completion ----
    if (tid == 0) {
        while (atomicAdd(&g_done, 0) < PREP_TOTAL) __nanosleep(64);
    }
    __syncthreads();
    __threadfence();

    // ---- Phase 2: walk. seg = w, row = lane. 16 quad-gathers ----
    int p = s_ps[lane][w];
    uint64_t word = (uint64_t)s_words[lane][2 * w + 0]
                  | ((uint64_t)s_words[lane][2 * w + 1] << 32);

    const __half* __restrict__ T = g_T4 + (size_t)(w * 16) * 8192;
    unsigned hq = (unsigned)p << 4;          // running index, multiple of 16
    float acc0 = 0.f, acc1 = 0.f;

    #pragma unroll
    for (int k = 0; k < 16; ++k) {
        unsigned c = (unsigned)(word >> (4 * k)) & 15u;
        float v = __half2float(__ldg(&T[k * 8192 + (hq | c)]));
        if (k & 1) acc1 += v; else acc0 += v;
        hq += (unsigned)__popc(c) << 4;
    }

    float acc = acc0 + acc1;
    if (w == NSEG - 1) acc += g_logE[hq >> 4];   // total popcount
    s_part[w][lane] = acc;
    __syncthreads();

    // ---- Phase 3: fixed-order reduce ----
    if (w == 0) {
        float s = 0.f;
        #pragma unroll
        for (int j = 0; j < NSEG; ++j) s += s_part[j][lane];
        out[r0 + lane] = s;
    }

    // ---- Reset barrier state for the next graph replay (deterministic) ----
    if (tid == 0) {
        int f = atomicAdd(&g_fin, 1);
        if (f == (int)gridDim.x - 1) {
            g_done = 0;
            __threadfence();
            g_fin = 0;
        }
    }
}

// ---------------------------------------------------------------------------
extern "C" void kernel_launch(void* const* d_in, const int* in_sizes, int n_in,
                              void* d_out, int out_size) {
    const int*   x    = (const int*)  d_in[0];   // (65536, 512) int32
    const float* W    = (const float*)d_in[1];   // (511, 512, 2) float32
    const float* endW = (const float*)d_in[2];   // (1, 513) float32
    float* out = (float*)d_out;

    (void)in_sizes; (void)n_in; (void)out_size;

    mega_kernel<<<BATCH / RPB, 256>>>(x, W, endW, out);
}